// round 11
// baseline (speedup 1.0000x reference)
#include <cuda_runtime.h>

// MultiStageFIRFilter: y = x + sum_{a=1..20} xa_a,
//   xa_a[b,t] = (1/a) * sum_{k=0..24} mc[b,t,k] * xa_{a-1}[b,t-k]  (xa_0 = x, causal)
//
// Fused halo-recompute kernel, 512 threads, R=2, barrier per stage.
// Window dedup: the 12 non-own window PAIRS of thread l are the (u0,u1) stage
// outputs of lanes l-12..l-1 -> fetched via __shfl_up_sync (register file, no
// L1tex queue). Only lanes l < delta cross the warp boundary and fall back to
// predicated LDS.64 from the stage buffer. Cuts smem wavefronts/stage ~2x and
// removes the 13x-redundant load queue that gated every previous variant.

#define NB      4
#define NT      16384
#define M       25
#define STAGES  20
#define HALO    480       // STAGES * 24
#define THREADS 512
#define EXT     1024      // 2 positions per thread
#define TILE    544       // EXT - HALO
#define PAD     24
#define NTILES  31        // ceil(16384 / 544)

__device__ __forceinline__ unsigned long long fma2(unsigned long long a,
                                                   unsigned long long b,
                                                   unsigned long long c) {
    unsigned long long d;
    asm("fma.rn.f32x2 %0, %1, %2, %3;" : "=l"(d) : "l"(a), "l"(b), "l"(c));
    return d;
}
__device__ __forceinline__ unsigned long long pack2(float lo, float hi) {
    unsigned long long d;
    asm("mov.b64 %0, {%1, %2};" : "=l"(d) : "f"(lo), "f"(hi));
    return d;
}
__device__ __forceinline__ void unpack2(unsigned long long v, float& lo, float& hi) {
    asm("mov.b64 {%0, %1}, %2;" : "=f"(lo), "=f"(hi) : "l"(v));
}

__global__ __launch_bounds__(THREADS, 1)
void fir_kernel(const float* __restrict__ x, const float* __restrict__ mc,
                float* __restrict__ out)
{
    __shared__ __align__(16) float s0[PAD + EXT];
    __shared__ __align__(16) float s1[PAD + EXT];

    const int tile = blockIdx.x % NTILES;
    const int b    = blockIdx.x / NTILES;
    const int t0   = tile * TILE;
    const int tid  = threadIdx.x;
    const int lane = tid & 31;
    const int i0   = 2 * tid;              // local position (even)
    const int p0   = t0 - HALO + i0;       // global time of first owned position
    const size_t rowbase = (size_t)b * NT;
    const bool valid = (p0 >= 0 && p0 + 1 < NT);   // p0 even -> both rows or neither

    if (tid < PAD) { s0[tid] = 0.0f; s1[tid] = 0.0f; }   // ghost zeros, both buffers

    // ---- coefficients (rows p0, p0+1 = 50 contiguous floats) ----
    // Invalid rows get c = 0 -> acc = 0 exactly (covers global ghosts / overhang).
    float c0[25], c1[25];
    if (valid) {
        const float2* g = (const float2*)(mc + (rowbase + (size_t)p0) * M);  // 8B-aligned
        float t[50];
        #pragma unroll
        for (int k = 0; k < 25; k++) { float2 v2 = g[k]; t[2*k] = v2.x; t[2*k+1] = v2.y; }
        #pragma unroll
        for (int k = 0; k < 25; k++) { c0[k] = t[k]; c1[k] = t[25 + k]; }
    } else {
        #pragma unroll
        for (int k = 0; k < 25; k++) { c0[k] = 0.0f; c1[k] = 0.0f; }
    }
    // Ascending window pairs: W[m] = val(i0-24+m), P[j] = (W[2j], W[2j+1]).
    // out0 (pos i0):   W[2j] is tap k=24-2j, W[2j+1] is tap k=23-2j.
    // out1 (pos i0+1): W[2j] is tap k=25-2j (j=0 -> k=25 invalid -> coeff 0),
    //                  W[2j+1] is tap k=24-2j.
    unsigned long long cp0[12], cp1[12];
    #pragma unroll
    for (int j = 0; j < 12; j++) {
        cp0[j] = pack2(c0[24 - 2*j], c0[23 - 2*j]);
        cp1[j] = pack2((j == 0) ? 0.0f : c1[25 - 2*j], c1[24 - 2*j]);
    }
    const float c00 = c0[0];   // out0 end: k=0 uses v0
    const float c11 = c1[1];   // out1 ends: k=1 uses v0, k=0 uses v1
    const float c10 = c1[0];

    // ---- stage 0: xa = x ----
    float u0, u1, y0, y1;
    if (valid) {
        const float2 xv = *(const float2*)(x + rowbase + p0);
        u0 = xv.x; u1 = xv.y;
    } else { u0 = 0.0f; u1 = 0.0f; }
    y0 = u0; y1 = u1;

    *(float2*)(s0 + PAD + i0) = make_float2(u0, u1);
    __syncthreads();

    float* cur = s0;
    float* nxt = s1;

    #pragma unroll
    for (int a = 1; a <= STAGES; a++) {
        const float inv = 1.0f / (float)a;          // compile-time constant (unrolled)

        // Window pairs P[j] = (val(i0-24+2j), val(i0-24+2j+1)) of stage a-1,
        // j = 0..11: = (u0,u1) of lane l - (12-j)  -> shfl_up, uniform delta.
        // Lanes l < delta cross the warp boundary -> predicated LDS.64 from cur.
        float2 P[12];
        #pragma unroll
        for (int j = 0; j < 12; j++) {
            const int delta = 12 - j;
            const float sa = __shfl_up_sync(0xffffffffu, u0, delta);
            const float sb = __shfl_up_sync(0xffffffffu, u1, delta);
            if (lane < delta) {
                // position i0-24+2j lives at smem index PAD + i0-24+2j = i0+2j
                P[j] = *(const float2*)(cur + i0 + 2*j);
            } else {
                P[j].x = sa; P[j].y = sb;
            }
        }

        unsigned long long A0 = 0ull, B0 = 0ull, A1 = 0ull, B1 = 0ull;
        #pragma unroll
        for (int j = 0; j < 12; j += 2) {           // even j -> chain A
            const unsigned long long Pv = pack2(P[j].x, P[j].y);
            A0 = fma2(cp0[j], Pv, A0);
            A1 = fma2(cp1[j], Pv, A1);
        }
        #pragma unroll
        for (int j = 1; j < 12; j += 2) {           // odd j -> chain B
            const unsigned long long Pv = pack2(P[j].x, P[j].y);
            B0 = fma2(cp0[j], Pv, B0);
            B1 = fma2(cp1[j], Pv, B1);
        }
        float a0l, a0h, b0l, b0h, a1l, a1h, b1l, b1h;
        unpack2(A0, a0l, a0h); unpack2(B0, b0l, b0h);
        unpack2(A1, a1l, a1h); unpack2(B1, b1l, b1h);

        const float out0 = fmaf(c00, u0, (a0l + b0l) + (a0h + b0h)) * inv;
        const float out1 = fmaf(c11, u0, fmaf(c10, u1, (a1l + b1l) + (a1h + b1h))) * inv;

        y0 += out0; y1 += out1;
        u0 = out0;  u1 = out1;
        *(float2*)(nxt + PAD + i0) = make_float2(u0, u1);

        __syncthreads();
        float* tmp = cur; cur = nxt; nxt = tmp;
    }

    // ---- write owned (non-halo) outputs ----
    if (i0 >= HALO && p0 < NT) {                    // valid by construction here
        *(float2*)(out + rowbase + p0) = make_float2(y0, y1);
    }
}

extern "C" void kernel_launch(void* const* d_in, const int* in_sizes, int n_in,
                              void* d_out, int out_size)
{
    const float* x  = (const float*)d_in[0];   // (4, 16384) float32
    const float* mc = (const float*)d_in[1];   // (4, 16384, 25) float32
    float* out = (float*)d_out;                // (4, 16384) float32
    fir_kernel<<<NB * NTILES, THREADS>>>(x, mc, out);
}

// round 13
// speedup vs baseline: 1.1382x; 1.1382x over previous
#include <cuda_runtime.h>

// MultiStageFIRFilter: y = x + sum_{a=1..20} xa_a,
//   xa_a[b,t] = (1/a) * sum_{k=0..24} mc[b,t,k] * xa_{a-1}[b,t-k]  (xa_0 = x, causal)
//
// R4 base (256 threads, R=4 positions/thread, float4 shared traffic, barrier
// per stage) + packed fma.rn.f32x2: the 12 ascending window PAIRS
// P[j]=(W[2j],W[2j+1]), W[m]=val(i0-24+m), are shared by all 4 outputs; each
// output r uses shifted coefficient pairs cp_r[j]=(c_r[24+r-2j], c_r[23+r-2j])
// (out-of-range -> 0), and own values form P[12]=(v0,v1), P[13]=(v2,v3).
// Halves FMA issue slots vs R4 with identical shared traffic.

#define NB      4
#define NT      16384
#define M       25
#define STAGES  20
#define HALO    480       // STAGES * 24
#define THREADS 256
#define R       4
#define EXT     1024      // THREADS * R
#define TILE    544       // EXT - HALO
#define PAD     24
#define NTILES  31        // ceil(16384 / 544)

typedef unsigned long long u64;

__device__ __forceinline__ u64 fma2(u64 a, u64 b, u64 c) {
    u64 d;
    asm("fma.rn.f32x2 %0, %1, %2, %3;" : "=l"(d) : "l"(a), "l"(b), "l"(c));
    return d;
}
__device__ __forceinline__ u64 pack2(float lo, float hi) {
    u64 d;
    asm("mov.b64 %0, {%1, %2};" : "=l"(d) : "f"(lo), "f"(hi));
    return d;
}
__device__ __forceinline__ void unpack2(u64 v, float& lo, float& hi) {
    asm("mov.b64 {%0, %1}, %2;" : "=f"(lo), "=f"(hi) : "l"(v));
}

__global__ __launch_bounds__(THREADS, 1)
void fir_kernel(const float* __restrict__ x, const float* __restrict__ mc,
                float* __restrict__ out)
{
    __shared__ __align__(16) float s0[PAD + EXT];
    __shared__ __align__(16) float s1[PAD + EXT];

    const int tile = blockIdx.x % NTILES;
    const int b    = blockIdx.x / NTILES;
    const int t0   = tile * TILE;
    const int tid  = threadIdx.x;
    const int i0   = R * tid;              // local position (multiple of 4)
    const int p0   = t0 - HALO + i0;       // global time of first owned position
    const size_t rowbase = (size_t)b * NT;
    const bool valid = (p0 >= 0 && p0 + R - 1 < NT);   // rows all-valid or all-not

    if (tid < PAD) { s0[tid] = 0.0f; s1[tid] = 0.0f; }

    // ---- coefficients: rows p0..p0+3 are 100 contiguous floats (16B-aligned) ----
    // Invalid rows get c = 0 -> acc = 0 exactly (covers ghosts and overhang).
    float c[100];                          // c[25*r + k] = mc[p0+r][k]
    if (valid) {
        const float4* g = (const float4*)(mc + (rowbase + (size_t)p0) * M);
        #pragma unroll
        for (int k = 0; k < 25; k++) {
            float4 v4 = g[k];
            c[4*k] = v4.x; c[4*k+1] = v4.y; c[4*k+2] = v4.z; c[4*k+3] = v4.w;
        }
    } else {
        #pragma unroll
        for (int j = 0; j < 100; j++) c[j] = 0.0f;
    }

    // ---- pack shifted coefficient pairs ----
    // out r (pos i0+r) = sum_j fma2(cp_r[j], P[j]) over its active j range:
    //   pair j covers (W[2j], W[2j+1]) with coeffs (c_r[24+r-2j], c_r[23+r-2j]).
    //   r=0: j=0..12   r=1: j=0..12   r=2: j=1..13   r=3: j=1..13
    u64 cp0[13], cp1[13], cp2[13], cp3[13];
    {
        #pragma unroll
        for (int j = 0; j <= 12; j++) {
            const int a0 = 24 - 2*j, b0_ = 23 - 2*j;          // r = 0
            cp0[j] = pack2(a0 >= 0 ? c[a0] : 0.0f, b0_ >= 0 ? c[b0_] : 0.0f);
            const int a1 = 25 - 2*j, b1_ = 24 - 2*j;          // r = 1
            cp1[j] = pack2(a1 <= 24 ? c[25 + a1] : 0.0f, c[25 + b1_]);
        }
        #pragma unroll
        for (int j = 1; j <= 13; j++) {
            const int a2 = 26 - 2*j, b2_ = 25 - 2*j;          // r = 2
            cp2[j-1] = pack2((a2 >= 0 && a2 <= 24) ? c[50 + a2] : 0.0f,
                             (b2_ >= 0 && b2_ <= 24) ? c[50 + b2_] : 0.0f);
            const int a3 = 27 - 2*j, b3_ = 26 - 2*j;          // r = 3
            cp3[j-1] = pack2((a3 >= 0 && a3 <= 24) ? c[75 + a3] : 0.0f,
                             (b3_ >= 0 && b3_ <= 24) ? c[75 + b3_] : 0.0f);
        }
    }

    // ---- stage 0: xa = x ----
    float v[R], y[R];
    if (valid) {
        const float4 xv = *(const float4*)(x + rowbase + p0);
        v[0] = xv.x; v[1] = xv.y; v[2] = xv.z; v[3] = xv.w;
    } else {
        #pragma unroll
        for (int r = 0; r < R; r++) v[r] = 0.0f;
    }
    #pragma unroll
    for (int r = 0; r < R; r++) y[r] = v[r];

    *((float4*)(s0 + PAD + i0)) = make_float4(v[0], v[1], v[2], v[3]);
    __syncthreads();

    float* cur = s0;
    float* nxt = s1;

    #pragma unroll
    for (int a = 1; a <= STAGES; a++) {
        const float inv = 1.0f / (float)a;         // compile-time constant
        if (tid >= 6 * a) {                        // exactness trim: need pos >= 24a
            // window pairs: W[m]=val(i0-24+m) at smem index i0+m (PAD folded in);
            // 6x LDS.128, 16B-aligned.
            u64 P[14];
            const float4* wp = (const float4*)(cur + i0);
            #pragma unroll
            for (int j = 0; j < 6; j++) {
                float4 q = wp[j];
                P[2*j]     = pack2(q.x, q.y);
                P[2*j + 1] = pack2(q.z, q.w);
            }
            P[12] = pack2(v[0], v[1]);             // (W[24], W[25])
            P[13] = pack2(v[2], v[3]);             // (W[26], W[27])

            // 8 independent fma2 chains (2 per output)
            u64 A0 = 0, B0 = 0, A1 = 0, B1 = 0, A2 = 0, B2 = 0, A3 = 0, B3 = 0;
            #pragma unroll
            for (int j = 0; j <= 12; j += 2) {     // even j
                A0 = fma2(cp0[j], P[j], A0);
                A1 = fma2(cp1[j], P[j], A1);
            }
            #pragma unroll
            for (int j = 1; j <= 12; j += 2) {     // odd j
                B0 = fma2(cp0[j], P[j], B0);
                B1 = fma2(cp1[j], P[j], B1);
            }
            #pragma unroll
            for (int j = 1; j <= 13; j += 2) {     // odd j (r=2,3 range starts at 1)
                A2 = fma2(cp2[j-1], P[j], A2);
                A3 = fma2(cp3[j-1], P[j], A3);
            }
            #pragma unroll
            for (int j = 2; j <= 13; j += 2) {     // even j
                B2 = fma2(cp2[j-1], P[j], B2);
                B3 = fma2(cp3[j-1], P[j], B3);
            }

            float l0, h0, l1, h1, acc[R];
            unpack2(A0, l0, h0); unpack2(B0, l1, h1);
            acc[0] = ((l0 + l1) + (h0 + h1)) * inv;
            unpack2(A1, l0, h0); unpack2(B1, l1, h1);
            acc[1] = ((l0 + l1) + (h0 + h1)) * inv;
            unpack2(A2, l0, h0); unpack2(B2, l1, h1);
            acc[2] = ((l0 + l1) + (h0 + h1)) * inv;
            unpack2(A3, l0, h0); unpack2(B3, l1, h1);
            acc[3] = ((l0 + l1) + (h0 + h1)) * inv;

            #pragma unroll
            for (int r = 0; r < R; r++) { y[r] += acc[r]; v[r] = acc[r]; }
            *((float4*)(nxt + PAD + i0)) = make_float4(v[0], v[1], v[2], v[3]);
        }
        __syncthreads();
        float* tmp = cur; cur = nxt; nxt = tmp;
    }

    // ---- write owned (non-halo) outputs ----
    if (i0 >= HALO && p0 < NT) {                   // valid here by construction
        *((float4*)(out + rowbase + p0)) = make_float4(y[0], y[1], y[2], y[3]);
    }
}

extern "C" void kernel_launch(void* const* d_in, const int* in_sizes, int n_in,
                              void* d_out, int out_size)
{
    const float* x  = (const float*)d_in[0];   // (4, 16384) float32
    const float* mc = (const float*)d_in[1];   // (4, 16384, 25) float32
    float* out = (float*)d_out;                // (4, 16384) float32
    fir_kernel<<<NB * NTILES, THREADS>>>(x, mc, out);
}